// round 6
// baseline (speedup 1.0000x reference)
#include <cuda_runtime.h>
#include <math.h>

#define B_   4
#define N_   2048
#define D_   512
#define H_   8
#define DH_  64
#define SCALE_ 0.125f
#define PADK 36
#define PK   68   // Ks / Ps stride: 4g+tig conflict-free frag loads
#define PV   72   // Vs stride: 8tig+g conflict-free frag loads
#define CMAX 10.0f

// -------- scratch (static device allocations; no cudaMalloc allowed) --------
__device__ float g_Q[B_*H_*N_*DH_];
__device__ float g_K[B_*H_*N_*DH_];
__device__ float g_V[B_*H_*N_*DH_];
__device__ float g_O[B_*N_*D_];

// -------- helpers --------
__device__ __forceinline__ unsigned f2tf(float x) {
    unsigned r; asm("cvt.rna.tf32.f32 %0, %1;" : "=r"(r) : "f"(x)); return r;
}
__device__ __forceinline__ float ftf(float x) { return __uint_as_float(f2tf(x)); }

__device__ __forceinline__ void mma_tf32(float* d, const unsigned* a, const unsigned* b) {
    asm volatile(
        "mma.sync.aligned.m16n8k8.row.col.f32.tf32.tf32.f32 "
        "{%0,%1,%2,%3}, {%4,%5,%6,%7}, {%8,%9}, {%0,%1,%2,%3};\n"
        : "+f"(d[0]), "+f"(d[1]), "+f"(d[2]), "+f"(d[3])
        : "r"(a[0]), "r"(a[1]), "r"(a[2]), "r"(a[3]),
          "r"(b[0]), "r"(b[1]));
}

__device__ __forceinline__ float4 tf4(float4 v) {
    v.x = ftf(v.x); v.y = ftf(v.y); v.z = ftf(v.z); v.w = ftf(v.w);
    return v;
}

// ============================================================================
// GEMM: Y[m,o] = sum_k X[m,k] * W[o,k] + bias[o]   (unchanged from R1)
// ============================================================================
__global__ __launch_bounds__(256) void gemm_tf32_kernel(
    const float* __restrict__ X, const float* __restrict__ W,
    const float* __restrict__ bias, float* __restrict__ Y,
    int mode, float scale)
{
    __shared__ float As[128][PADK];
    __shared__ float Bs[64][PADK];

    const int m0 = blockIdx.x * 128, n0 = blockIdx.y * 64;
    const int tid = threadIdx.x, lane = tid & 31, wid = tid >> 5;
    const int g = lane >> 2, tig = lane & 3;
    const int wm = wid >> 1, wn = wid & 1;

    float acc[2][4][4];
#pragma unroll
    for (int i = 0; i < 2; i++)
#pragma unroll
        for (int j = 0; j < 4; j++)
#pragma unroll
            for (int k = 0; k < 4; k++) acc[i][j][k] = 0.f;

    const int ar = tid >> 3, ac = (tid & 7) * 4;

    for (int k0 = 0; k0 < 512; k0 += 32) {
#pragma unroll
        for (int p = 0; p < 4; p++) {
            int r = ar + 32 * p;
            float4 v = *(const float4*)(X + (size_t)(m0 + r) * 512 + k0 + ac);
            As[r][ac + 0] = ftf(v.x); As[r][ac + 1] = ftf(v.y);
            As[r][ac + 2] = ftf(v.z); As[r][ac + 3] = ftf(v.w);
        }
#pragma unroll
        for (int p = 0; p < 2; p++) {
            int r = ar + 32 * p;
            if (r < 64) {
                float4 v = *(const float4*)(W + (size_t)(n0 + r) * 512 + k0 + ac);
                Bs[r][ac + 0] = ftf(v.x); Bs[r][ac + 1] = ftf(v.y);
                Bs[r][ac + 2] = ftf(v.z); Bs[r][ac + 3] = ftf(v.w);
            }
        }
        __syncthreads();

#pragma unroll
        for (int ks = 0; ks < 4; ks++) {
            unsigned a[2][4], b[4][2];
#pragma unroll
            for (int mt = 0; mt < 2; mt++) {
                int r = wm * 32 + mt * 16 + g;
                a[mt][0] = __float_as_uint(As[r][ks * 8 + tig]);
                a[mt][1] = __float_as_uint(As[r + 8][ks * 8 + tig]);
                a[mt][2] = __float_as_uint(As[r][ks * 8 + tig + 4]);
                a[mt][3] = __float_as_uint(As[r + 8][ks * 8 + tig + 4]);
            }
#pragma unroll
            for (int nt = 0; nt < 4; nt++) {
                int c = wn * 32 + nt * 8 + g;
                b[nt][0] = __float_as_uint(Bs[c][ks * 8 + tig]);
                b[nt][1] = __float_as_uint(Bs[c][ks * 8 + tig + 4]);
            }
#pragma unroll
            for (int mt = 0; mt < 2; mt++)
#pragma unroll
                for (int nt = 0; nt < 4; nt++)
                    mma_tf32(acc[mt][nt], a[mt], b[nt]);
        }
        __syncthreads();
    }

#pragma unroll
    for (int mt = 0; mt < 2; mt++) {
#pragma unroll
        for (int nt = 0; nt < 4; nt++) {
            int cb = n0 + wn * 32 + nt * 8 + tig * 2;
#pragma unroll
            for (int rr = 0; rr < 2; rr++) {
                int r = m0 + wm * 32 + mt * 16 + g + rr * 8;
#pragma unroll
                for (int cc = 0; cc < 2; cc++) {
                    int c = cb + cc;
                    float v = (acc[mt][nt][rr * 2 + cc] + bias[c]) * scale;
                    if (mode == 0) {
                        Y[(size_t)r * 512 + c] = v;
                    } else {
                        int bb = r >> 11, nn = r & 2047;
                        int hh = c >> 6, dd = c & 63;
                        Y[((size_t)(bb * 8 + hh) * 2048 + nn) * 64 + dd] = v;
                    }
                }
            }
        }
    }
}

// ============================================================================
// Fused attention, exp-normalize form (no online max):
//   p = sigmoid(gw*SC+gb) * exp(s - CMAX);  O = (sum p V) / (sum p)
// grid (N/64, H, B); 256 threads = 8 warps (4m x 2n), warp tile 16x32.
// ============================================================================
__global__ __launch_bounds__(256, 2) void attn_kernel(
    const float* __restrict__ SC,
    const float* __restrict__ gwp, const float* __restrict__ gbp)
{
    extern __shared__ float smf[];
    float* Ks = smf;            // 64*PK
    float* Vs = Ks + 64 * PK;   // 64*PV
    float* Ps = Vs + 64 * PV;   // 64*PK  (also Q staging at start)
    __shared__ float Lred[64][2];

    const int q0 = blockIdx.x * 64, h = blockIdx.y, b = blockIdx.z;
    const int tid = threadIdx.x, lane = tid & 31, wid = tid >> 5;
    const int g = lane >> 2, tig = lane & 3;
    const int wm = wid >> 1, wn = wid & 1;
    const int rowa = wm * 16 + g;

    const float gw = *gwp, gb = *gbp;

    const float* Qg = g_Q + ((size_t)(b * 8 + h) * 2048 + q0) * 64;
    const float* Kg = g_K + ((size_t)(b * 8 + h) * 2048) * 64;
    const float* Vg = g_V + ((size_t)(b * 8 + h) * 2048) * 64;

    const int rr0 = tid >> 4;         // 0..15
    const int cst = (tid & 15) * 4;   // 0..60

    // stage Q into Ps, hoist fragments
#pragma unroll
    for (int p = 0; p < 4; p++) {
        int rr = rr0 + 16 * p;
        float4 v = tf4(*(const float4*)(Qg + (size_t)rr * 64 + cst));
        *(float4*)(Ps + rr * PK + cst) = v;
    }
    __syncthreads();

    unsigned aq[8][4];
#pragma unroll
    for (int ks = 0; ks < 8; ks++) {
        aq[ks][0] = __float_as_uint(Ps[rowa * PK + ks * 8 + tig]);
        aq[ks][1] = __float_as_uint(Ps[(rowa + 8) * PK + ks * 8 + tig]);
        aq[ks][2] = __float_as_uint(Ps[rowa * PK + ks * 8 + tig + 4]);
        aq[ks][3] = __float_as_uint(Ps[(rowa + 8) * PK + ks * 8 + tig + 4]);
    }

    float oacc[4][4];
#pragma unroll
    for (int i = 0; i < 4; i++)
#pragma unroll
        for (int j = 0; j < 4; j++) oacc[i][j] = 0.f;
    float psum0 = 0.f, psum1 = 0.f;

    // prefetch tile 0 into registers
    float4 kf[4], vf[4];
#pragma unroll
    for (int p = 0; p < 4; p++) {
        int rr = rr0 + 16 * p;
        kf[p] = *(const float4*)(Kg + (size_t)rr * 64 + cst);
        vf[p] = *(const float4*)(Vg + (size_t)rr * 64 + cst);
    }

    for (int kt0 = 0; kt0 < 2048; kt0 += 64) {
        // store prefetched tile (barrier at end of prev iter protects smem)
#pragma unroll
        for (int p = 0; p < 4; p++) {
            int rr = rr0 + 16 * p;
            *(float4*)(Ks + rr * PK + cst) = tf4(kf[p]);
            *(float4*)(Vs + rr * PV + cst) = tf4(vf[p]);
        }
        __syncthreads();

        // prefetch next tile (latency overlaps mma + softmax)
        if (kt0 + 64 < 2048) {
#pragma unroll
            for (int p = 0; p < 4; p++) {
                int rr = kt0 + 64 + rr0 + 16 * p;
                kf[p] = *(const float4*)(Kg + (size_t)rr * 64 + cst);
                vf[p] = *(const float4*)(Vg + (size_t)rr * 64 + cst);
            }
        }

        // S = Q * K^T
        float sfr[4][4];
#pragma unroll
        for (int i = 0; i < 4; i++)
#pragma unroll
            for (int j = 0; j < 4; j++) sfr[i][j] = 0.f;
#pragma unroll
        for (int ks = 0; ks < 8; ks++) {
#pragma unroll
            for (int nt = 0; nt < 4; nt++) {
                unsigned bk[2];
                int c = wn * 32 + nt * 8 + g;
                bk[0] = __float_as_uint(Ks[c * PK + ks * 8 + tig]);
                bk[1] = __float_as_uint(Ks[c * PK + ks * 8 + tig + 4]);
                mma_tf32(sfr[nt], aq[ks], bk);
            }
        }

        // p = sigmoid(gw*sc+gb) * exp(s - CMAX); accumulate row sums; store P
#pragma unroll
        for (int nt = 0; nt < 4; nt++) {
            int c0 = wn * 32 + nt * 8 + tig * 2;
#pragma unroll
            for (int rr = 0; rr < 2; rr++) {
                int r = rowa + rr * 8;
                float2 sc = *(const float2*)(SC + ((size_t)b * 2048 + q0 + r) * 2048 + kt0 + c0);
                float g0 = __fdividef(1.f, 1.f + __expf(-fmaf(gw, sc.x, gb)));
                float g1 = __fdividef(1.f, 1.f + __expf(-fmaf(gw, sc.y, gb)));
                float p0 = g0 * __expf(sfr[nt][rr * 2 + 0] - CMAX);
                float p1 = g1 * __expf(sfr[nt][rr * 2 + 1] - CMAX);
                if (rr == 0) psum0 += p0 + p1; else psum1 += p0 + p1;
                float2 pw; pw.x = ftf(p0); pw.y = ftf(p1);
                *(float2*)(Ps + r * PK + c0) = pw;
            }
        }
        __syncthreads();

        // O += P * V
#pragma unroll
        for (int ks = 0; ks < 8; ks++) {
            unsigned ap[4];
            ap[0] = __float_as_uint(Ps[rowa * PK + ks * 8 + tig]);
            ap[1] = __float_as_uint(Ps[(rowa + 8) * PK + ks * 8 + tig]);
            ap[2] = __float_as_uint(Ps[rowa * PK + ks * 8 + tig + 4]);
            ap[3] = __float_as_uint(Ps[(rowa + 8) * PK + ks * 8 + tig + 4]);
#pragma unroll
            for (int nt = 0; nt < 4; nt++) {
                unsigned bv[2];
                int c = wn * 32 + nt * 8 + g;
                bv[0] = __float_as_uint(Vs[(ks * 8 + tig) * PV + c]);
                bv[1] = __float_as_uint(Vs[(ks * 8 + tig + 4) * PV + c]);
                mma_tf32(oacc[nt], ap, bv);
            }
        }
        __syncthreads();   // protect Ks/Vs/Ps before next iter's stores
    }

    // final row-sum reduction: over tig (shfl) then across wn (smem)
    psum0 += __shfl_xor_sync(0xffffffffu, psum0, 1);
    psum0 += __shfl_xor_sync(0xffffffffu, psum0, 2);
    psum1 += __shfl_xor_sync(0xffffffffu, psum1, 1);
    psum1 += __shfl_xor_sync(0xffffffffu, psum1, 2);
    if (tig == 0) { Lred[rowa][wn] = psum0; Lred[rowa + 8][wn] = psum1; }
    __syncthreads();
    float il1 = __fdividef(1.f, Lred[rowa][0] + Lred[rowa][1]);
    float il2 = __fdividef(1.f, Lred[rowa + 8][0] + Lred[rowa + 8][1]);

#pragma unroll
    for (int nt = 0; nt < 4; nt++) {
        int c = h * 64 + wn * 32 + nt * 8 + tig * 2;
        float* o1 = g_O + ((size_t)b * 2048 + q0 + rowa) * 512 + c;
        float* o2 = g_O + ((size_t)b * 2048 + q0 + rowa + 8) * 512 + c;
        o1[0] = oacc[nt][0] * il1; o1[1] = oacc[nt][1] * il1;
        o2[0] = oacc[nt][2] * il2; o2[1] = oacc[nt][3] * il2;
    }
}

// ============================================================================
extern "C" void kernel_launch(void* const* d_in, const int* in_sizes, int n_in,
                              void* d_out, int out_size)
{
    (void)in_sizes; (void)n_in; (void)out_size;
    const float* Qin  = (const float*)d_in[0];
    const float* KVin = (const float*)d_in[1];
    const float* SC   = (const float*)d_in[2];
    const float* Wq   = (const float*)d_in[3];
    const float* Wqb  = (const float*)d_in[4];
    const float* Wk   = (const float*)d_in[5];
    const float* Wkb  = (const float*)d_in[6];
    const float* Wv   = (const float*)d_in[7];
    const float* Wvb  = (const float*)d_in[8];
    const float* gw   = (const float*)d_in[9];
    const float* gb   = (const float*)d_in[10];
    const float* Wo   = (const float*)d_in[11];
    const float* Wob  = (const float*)d_in[12];
    float* out = (float*)d_out;

    float *Qp, *Kp, *Vp, *Op;
    cudaGetSymbolAddress((void**)&Qp, g_Q);
    cudaGetSymbolAddress((void**)&Kp, g_K);
    cudaGetSymbolAddress((void**)&Vp, g_V);
    cudaGetSymbolAddress((void**)&Op, g_O);

    size_t smem = (size_t)(64 * PK * 2 + 64 * PV) * sizeof(float);
    cudaFuncSetAttribute(attn_kernel, cudaFuncAttributeMaxDynamicSharedMemorySize, (int)smem);

    dim3 gg(N_ * B_ / 128, D_ / 64);   // (64, 8)
    gemm_tf32_kernel<<<gg, 256>>>(Qin,  Wq, Wqb, Qp, 1, SCALE_);
    gemm_tf32_kernel<<<gg, 256>>>(KVin, Wk, Wkb, Kp, 1, 1.0f);
    gemm_tf32_kernel<<<gg, 256>>>(KVin, Wv, Wvb, Vp, 1, 1.0f);

    attn_kernel<<<dim3(N_ / 64, H_, B_), 256, smem>>>(SC, gw, gb);

    gemm_tf32_kernel<<<gg, 256>>>(Op, Wo, Wob, out, 0, 1.0f);
}

// round 8
// speedup vs baseline: 1.0019x; 1.0019x over previous
#include <cuda_runtime.h>
#include <math.h>

#define B_   4
#define N_   2048
#define D_   512
#define H_   8
#define DH_  64
#define SCALE_ 0.125f
#define PADK 36
#define PK   68   // Ks / Ps stride: 4g+tig conflict-free frag loads
#define PV   72   // Vs stride: 8tig+g conflict-free frag loads
#define CMAX 10.0f

// -------- scratch (static device allocations; no cudaMalloc allowed) --------
__device__ float g_Q[B_*H_*N_*DH_];
__device__ float g_K[B_*H_*N_*DH_];
__device__ float g_V[B_*H_*N_*DH_];
__device__ float g_O[B_*N_*D_];

// -------- helpers --------
__device__ __forceinline__ unsigned f2tf(float x) {
    unsigned r; asm("cvt.rna.tf32.f32 %0, %1;" : "=r"(r) : "f"(x)); return r;
}
__device__ __forceinline__ float ftf(float x) { return __uint_as_float(f2tf(x)); }

__device__ __forceinline__ void mma_tf32(float* d, const unsigned* a, const unsigned* b) {
    asm volatile(
        "mma.sync.aligned.m16n8k8.row.col.f32.tf32.tf32.f32 "
        "{%0,%1,%2,%3}, {%4,%5,%6,%7}, {%8,%9}, {%0,%1,%2,%3};\n"
        : "+f"(d[0]), "+f"(d[1]), "+f"(d[2]), "+f"(d[3])
        : "r"(a[0]), "r"(a[1]), "r"(a[2]), "r"(a[3]),
          "r"(b[0]), "r"(b[1]));
}

__device__ __forceinline__ float4 tf4(float4 v) {
    v.x = ftf(v.x); v.y = ftf(v.y); v.z = ftf(v.z); v.w = ftf(v.w);
    return v;
}

// ============================================================================
// GEMM: Y[m,o] = sum_k X[m,k] * W[o,k] + bias[o]   (unchanged from R1)
// ============================================================================
__global__ __launch_bounds__(256) void gemm_tf32_kernel(
    const float* __restrict__ X, const float* __restrict__ W,
    const float* __restrict__ bias, float* __restrict__ Y,
    int mode, float scale)
{
    __shared__ float As[128][PADK];
    __shared__ float Bs[64][PADK];

    const int m0 = blockIdx.x * 128, n0 = blockIdx.y * 64;
    const int tid = threadIdx.x, lane = tid & 31, wid = tid >> 5;
    const int g = lane >> 2, tig = lane & 3;
    const int wm = wid >> 1, wn = wid & 1;

    float acc[2][4][4];
#pragma unroll
    for (int i = 0; i < 2; i++)
#pragma unroll
        for (int j = 0; j < 4; j++)
#pragma unroll
            for (int k = 0; k < 4; k++) acc[i][j][k] = 0.f;

    const int ar = tid >> 3, ac = (tid & 7) * 4;

    for (int k0 = 0; k0 < 512; k0 += 32) {
#pragma unroll
        for (int p = 0; p < 4; p++) {
            int r = ar + 32 * p;
            float4 v = *(const float4*)(X + (size_t)(m0 + r) * 512 + k0 + ac);
            As[r][ac + 0] = ftf(v.x); As[r][ac + 1] = ftf(v.y);
            As[r][ac + 2] = ftf(v.z); As[r][ac + 3] = ftf(v.w);
        }
#pragma unroll
        for (int p = 0; p < 2; p++) {
            int r = ar + 32 * p;
            if (r < 64) {
                float4 v = *(const float4*)(W + (size_t)(n0 + r) * 512 + k0 + ac);
                Bs[r][ac + 0] = ftf(v.x); Bs[r][ac + 1] = ftf(v.y);
                Bs[r][ac + 2] = ftf(v.z); Bs[r][ac + 3] = ftf(v.w);
            }
        }
        __syncthreads();

#pragma unroll
        for (int ks = 0; ks < 4; ks++) {
            unsigned a[2][4], b[4][2];
#pragma unroll
            for (int mt = 0; mt < 2; mt++) {
                int r = wm * 32 + mt * 16 + g;
                a[mt][0] = __float_as_uint(As[r][ks * 8 + tig]);
                a[mt][1] = __float_as_uint(As[r + 8][ks * 8 + tig]);
                a[mt][2] = __float_as_uint(As[r][ks * 8 + tig + 4]);
                a[mt][3] = __float_as_uint(As[r + 8][ks * 8 + tig + 4]);
            }
#pragma unroll
            for (int nt = 0; nt < 4; nt++) {
                int c = wn * 32 + nt * 8 + g;
                b[nt][0] = __float_as_uint(Bs[c][ks * 8 + tig]);
                b[nt][1] = __float_as_uint(Bs[c][ks * 8 + tig + 4]);
            }
#pragma unroll
            for (int mt = 0; mt < 2; mt++)
#pragma unroll
                for (int nt = 0; nt < 4; nt++)
                    mma_tf32(acc[mt][nt], a[mt], b[nt]);
        }
        __syncthreads();
    }

#pragma unroll
    for (int mt = 0; mt < 2; mt++) {
#pragma unroll
        for (int nt = 0; nt < 4; nt++) {
            int cb = n0 + wn * 32 + nt * 8 + tig * 2;
#pragma unroll
            for (int rr = 0; rr < 2; rr++) {
                int r = m0 + wm * 32 + mt * 16 + g + rr * 8;
#pragma unroll
                for (int cc = 0; cc < 2; cc++) {
                    int c = cb + cc;
                    float v = (acc[mt][nt][rr * 2 + cc] + bias[c]) * scale;
                    if (mode == 0) {
                        Y[(size_t)r * 512 + c] = v;
                    } else {
                        int bb = r >> 11, nn = r & 2047;
                        int hh = c >> 6, dd = c & 63;
                        Y[((size_t)(bb * 8 + hh) * 2048 + nn) * 64 + dd] = v;
                    }
                }
            }
        }
    }
}

// ============================================================================
// Fused attention, exp-normalize form (no online max):
//   p = sigmoid(gw*SC+gb) * exp(s - CMAX);  O = (sum p V) / (sum p)
// grid (N/64, H, B); 256 threads = 8 warps (4m x 2n), warp tile 16x32.
// ============================================================================
__global__ __launch_bounds__(256, 2) void attn_kernel(
    const float* __restrict__ SC,
    const float* __restrict__ gwp, const float* __restrict__ gbp)
{
    extern __shared__ float smf[];
    float* Ks = smf;            // 64*PK
    float* Vs = Ks + 64 * PK;   // 64*PV
    float* Ps = Vs + 64 * PV;   // 64*PK  (also Q staging at start)
    __shared__ float Lred[64][2];

    const int q0 = blockIdx.x * 64, h = blockIdx.y, b = blockIdx.z;
    const int tid = threadIdx.x, lane = tid & 31, wid = tid >> 5;
    const int g = lane >> 2, tig = lane & 3;
    const int wm = wid >> 1, wn = wid & 1;
    const int rowa = wm * 16 + g;

    const float gw = *gwp, gb = *gbp;

    const float* Qg = g_Q + ((size_t)(b * 8 + h) * 2048 + q0) * 64;
    const float* Kg = g_K + ((size_t)(b * 8 + h) * 2048) * 64;
    const float* Vg = g_V + ((size_t)(b * 8 + h) * 2048) * 64;

    const int rr0 = tid >> 4;         // 0..15
    const int cst = (tid & 15) * 4;   // 0..60

    // stage Q into Ps, hoist fragments
#pragma unroll
    for (int p = 0; p < 4; p++) {
        int rr = rr0 + 16 * p;
        float4 v = tf4(*(const float4*)(Qg + (size_t)rr * 64 + cst));
        *(float4*)(Ps + rr * PK + cst) = v;
    }
    __syncthreads();

    unsigned aq[8][4];
#pragma unroll
    for (int ks = 0; ks < 8; ks++) {
        aq[ks][0] = __float_as_uint(Ps[rowa * PK + ks * 8 + tig]);
        aq[ks][1] = __float_as_uint(Ps[(rowa + 8) * PK + ks * 8 + tig]);
        aq[ks][2] = __float_as_uint(Ps[rowa * PK + ks * 8 + tig + 4]);
        aq[ks][3] = __float_as_uint(Ps[(rowa + 8) * PK + ks * 8 + tig + 4]);
    }

    float oacc[4][4];
#pragma unroll
    for (int i = 0; i < 4; i++)
#pragma unroll
        for (int j = 0; j < 4; j++) oacc[i][j] = 0.f;
    float psum0 = 0.f, psum1 = 0.f;

    // prefetch tile 0 into registers
    float4 kf[4], vf[4];
#pragma unroll
    for (int p = 0; p < 4; p++) {
        int rr = rr0 + 16 * p;
        kf[p] = *(const float4*)(Kg + (size_t)rr * 64 + cst);
        vf[p] = *(const float4*)(Vg + (size_t)rr * 64 + cst);
    }

    for (int kt0 = 0; kt0 < 2048; kt0 += 64) {
        // store prefetched tile (barrier at end of prev iter protects smem)
#pragma unroll
        for (int p = 0; p < 4; p++) {
            int rr = rr0 + 16 * p;
            *(float4*)(Ks + rr * PK + cst) = tf4(kf[p]);
            *(float4*)(Vs + rr * PV + cst) = tf4(vf[p]);
        }
        __syncthreads();

        // prefetch next tile (latency overlaps mma + softmax)
        if (kt0 + 64 < 2048) {
#pragma unroll
            for (int p = 0; p < 4; p++) {
                int rr = kt0 + 64 + rr0 + 16 * p;
                kf[p] = *(const float4*)(Kg + (size_t)rr * 64 + cst);
                vf[p] = *(const float4*)(Vg + (size_t)rr * 64 + cst);
            }
        }

        // S = Q * K^T
        float sfr[4][4];
#pragma unroll
        for (int i = 0; i < 4; i++)
#pragma unroll
            for (int j = 0; j < 4; j++) sfr[i][j] = 0.f;
#pragma unroll
        for (int ks = 0; ks < 8; ks++) {
#pragma unroll
            for (int nt = 0; nt < 4; nt++) {
                unsigned bk[2];
                int c = wn * 32 + nt * 8 + g;
                bk[0] = __float_as_uint(Ks[c * PK + ks * 8 + tig]);
                bk[1] = __float_as_uint(Ks[c * PK + ks * 8 + tig + 4]);
                mma_tf32(sfr[nt], aq[ks], bk);
            }
        }

        // p = sigmoid(gw*sc+gb) * exp(s - CMAX); accumulate row sums; store P
#pragma unroll
        for (int nt = 0; nt < 4; nt++) {
            int c0 = wn * 32 + nt * 8 + tig * 2;
#pragma unroll
            for (int rr = 0; rr < 2; rr++) {
                int r = rowa + rr * 8;
                float2 sc = *(const float2*)(SC + ((size_t)b * 2048 + q0 + r) * 2048 + kt0 + c0);
                float g0 = __fdividef(1.f, 1.f + __expf(-fmaf(gw, sc.x, gb)));
                float g1 = __fdividef(1.f, 1.f + __expf(-fmaf(gw, sc.y, gb)));
                float p0 = g0 * __expf(sfr[nt][rr * 2 + 0] - CMAX);
                float p1 = g1 * __expf(sfr[nt][rr * 2 + 1] - CMAX);
                if (rr == 0) psum0 += p0 + p1; else psum1 += p0 + p1;
                float2 pw; pw.x = ftf(p0); pw.y = ftf(p1);
                *(float2*)(Ps + r * PK + c0) = pw;
            }
        }
        __syncthreads();

        // O += P * V
#pragma unroll
        for (int ks = 0; ks < 8; ks++) {
            unsigned ap[4];
            ap[0] = __float_as_uint(Ps[rowa * PK + ks * 8 + tig]);
            ap[1] = __float_as_uint(Ps[(rowa + 8) * PK + ks * 8 + tig]);
            ap[2] = __float_as_uint(Ps[rowa * PK + ks * 8 + tig + 4]);
            ap[3] = __float_as_uint(Ps[(rowa + 8) * PK + ks * 8 + tig + 4]);
#pragma unroll
            for (int nt = 0; nt < 4; nt++) {
                unsigned bv[2];
                int c = wn * 32 + nt * 8 + g;
                bv[0] = __float_as_uint(Vs[(ks * 8 + tig) * PV + c]);
                bv[1] = __float_as_uint(Vs[(ks * 8 + tig + 4) * PV + c]);
                mma_tf32(oacc[nt], ap, bv);
            }
        }
        __syncthreads();   // protect Ks/Vs/Ps before next iter's stores
    }

    // final row-sum reduction: over tig (shfl) then across wn (smem)
    psum0 += __shfl_xor_sync(0xffffffffu, psum0, 1);
    psum0 += __shfl_xor_sync(0xffffffffu, psum0, 2);
    psum1 += __shfl_xor_sync(0xffffffffu, psum1, 1);
    psum1 += __shfl_xor_sync(0xffffffffu, psum1, 2);
    if (tig == 0) { Lred[rowa][wn] = psum0; Lred[rowa + 8][wn] = psum1; }
    __syncthreads();
    float il1 = __fdividef(1.f, Lred[rowa][0] + Lred[rowa][1]);
    float il2 = __fdividef(1.f, Lred[rowa + 8][0] + Lred[rowa + 8][1]);

#pragma unroll
    for (int nt = 0; nt < 4; nt++) {
        int c = h * 64 + wn * 32 + nt * 8 + tig * 2;
        float* o1 = g_O + ((size_t)b * 2048 + q0 + rowa) * 512 + c;
        float* o2 = g_O + ((size_t)b * 2048 + q0 + rowa + 8) * 512 + c;
        o1[0] = oacc[nt][0] * il1; o1[1] = oacc[nt][1] * il1;
        o2[0] = oacc[nt][2] * il2; o2[1] = oacc[nt][3] * il2;
    }
}

// ============================================================================
extern "C" void kernel_launch(void* const* d_in, const int* in_sizes, int n_in,
                              void* d_out, int out_size)
{
    (void)in_sizes; (void)n_in; (void)out_size;
    const float* Qin  = (const float*)d_in[0];
    const float* KVin = (const float*)d_in[1];
    const float* SC   = (const float*)d_in[2];
    const float* Wq   = (const float*)d_in[3];
    const float* Wqb  = (const float*)d_in[4];
    const float* Wk   = (const float*)d_in[5];
    const float* Wkb  = (const float*)d_in[6];
    const float* Wv   = (const float*)d_in[7];
    const float* Wvb  = (const float*)d_in[8];
    const float* gw   = (const float*)d_in[9];
    const float* gb   = (const float*)d_in[10];
    const float* Wo   = (const float*)d_in[11];
    const float* Wob  = (const float*)d_in[12];
    float* out = (float*)d_out;

    float *Qp, *Kp, *Vp, *Op;
    cudaGetSymbolAddress((void**)&Qp, g_Q);
    cudaGetSymbolAddress((void**)&Kp, g_K);
    cudaGetSymbolAddress((void**)&Vp, g_V);
    cudaGetSymbolAddress((void**)&Op, g_O);

    size_t smem = (size_t)(64 * PK * 2 + 64 * PV) * sizeof(float);
    cudaFuncSetAttribute(attn_kernel, cudaFuncAttributeMaxDynamicSharedMemorySize, (int)smem);

    dim3 gg(N_ * B_ / 128, D_ / 64);   // (64, 8)
    gemm_tf32_kernel<<<gg, 256>>>(Qin,  Wq, Wqb, Qp, 1, SCALE_);
    gemm_tf32_kernel<<<gg, 256>>>(KVin, Wk, Wkb, Kp, 1, 1.0f);
    gemm_tf32_kernel<<<gg, 256>>>(KVin, Wv, Wvb, Vp, 1, 1.0f);

    attn_kernel<<<dim3(N_ / 64, H_, B_), 256, smem>>>(SC, gw, gb);

    gemm_tf32_kernel<<<gg, 256>>>(Op, Wo, Wob, out, 0, 1.0f);
}